// round 6
// baseline (speedup 1.0000x reference)
#include <cuda_runtime.h>

#define OUT_S 56
#define N_OUT 3136
#define NC_PER_GROUP 8192

// Separable AdaptiveAvgPool2d(56) from S in {24,32,48}: S/56 = NUM/7, NUM=S/8.
// Vertical windows of width 1 are pure copies of an h-pooled row -> stored
// directly from phase-A registers (no smem round trip). Width-2 rows are
// blended in phase B from register-cached strip rows.

__device__ __forceinline__ void store14(float* dst, const float* o, bool qodd)
{
    if (!qodd) {
        *(float4*)(dst + 0)  = make_float4(o[0],  o[1],  o[2],  o[3]);
        *(float4*)(dst + 4)  = make_float4(o[4],  o[5],  o[6],  o[7]);
        *(float4*)(dst + 8)  = make_float4(o[8],  o[9],  o[10], o[11]);
        *(float2*)(dst + 12) = make_float2(o[12], o[13]);
    } else {
        *(float2*)(dst + 0)  = make_float2(o[0],  o[1]);
        *(float4*)(dst + 2)  = make_float4(o[2],  o[3],  o[4],  o[5]);
        *(float4*)(dst + 6)  = make_float4(o[6],  o[7],  o[8],  o[9]);
        *(float4*)(dst + 10) = make_float4(o[10], o[11], o[12], o[13]);
    }
}

template<int S>
__device__ __forceinline__ void run_group(const float* __restrict__ src,
                                          float mean, float sd,
                                          float* __restrict__ hp,    // [S][56]
                                          float* __restrict__ outp,
                                          int tid)                   // 0..255
{
    constexpr int NUM = S / 8;      // 3, 4, 6
    constexpr int CPT = S / 4;      // 6, 8, 12

    // ---------------- Phase A: global -> regs -> h-pool ----------------
    if (tid < S * 4) {
        const int r = tid >> 2;
        const int q = tid & 3;
        const float* __restrict__ row = src + r * S + q * CPT;

        float v[CPT];
        if constexpr ((CPT & 3) == 0) {
            #pragma unroll
            for (int k = 0; k < CPT / 4; k++) {
                float4 t = ((const float4*)row)[k];
                v[4*k+0] = t.x; v[4*k+1] = t.y; v[4*k+2] = t.z; v[4*k+3] = t.w;
            }
        } else {
            #pragma unroll
            for (int k = 0; k < CPT / 2; k++) {
                float2 t = ((const float2*)row)[k];
                v[2*k+0] = t.x; v[2*k+1] = t.y;
            }
        }
        #pragma unroll
        for (int k = 0; k < CPT; k++)
            v[k] = fmaxf(fmaf(v[k], sd, mean), 0.0f);

        float o[14];
        #pragma unroll
        for (int jr = 0; jr < 14; jr++) {
            const int c0 = (jr * NUM) / 7;
            const int w  = ((jr + 1) * NUM + 6) / 7 - c0;
            o[jr] = (w == 2) ? (v[c0] + v[c0 + 1]) * 0.5f : v[c0];
        }

        // Direct global stores for width-1 vertical output rows served by r.
        const int strip = r / NUM;
        const int loc   = r - strip * NUM;
        float* orow = outp + (strip * 7) * 56 + q * 14;
        const bool qodd = (q & 1) != 0;
        #pragma unroll
        for (int i = 0; i < 7; i++) {
            const int r0 = (i * NUM) / 7;
            const int w  = ((i + 1) * NUM + 6) / 7 - r0;
            if (w == 1 && loc == r0)
                store14(orow + i * 56, o, qodd);
        }

        // Stage for phase B (all rows feed some width-2 output).
        store14(hp + r * 56 + q * 14, o, qodd);
    }
    __syncthreads();

    // ---------------- Phase B: width-2 rows only, register-cached strips ----
    if (tid < 112) {
        const int strip = tid / 14;          // 0..7
        const int jc    = tid - strip * 14;  // float4 column

        const float* base = hp + strip * (NUM * 56) + jc * 4;
        float4 rows[NUM];
        #pragma unroll
        for (int k = 0; k < NUM; k++)
            rows[k] = *(const float4*)(base + k * 56);

        float4* __restrict__ o4 = (float4*)outp + (strip * 7) * 14 + jc;
        #pragma unroll
        for (int i = 0; i < 7; i++) {
            const int r0 = (i * NUM) / 7;
            const int w  = ((i + 1) * NUM + 6) / 7 - r0;
            if (w == 2) {
                float4 res;
                res.x = (rows[r0].x + rows[r0+1].x) * 0.5f;
                res.y = (rows[r0].y + rows[r0+1].y) * 0.5f;
                res.z = (rows[r0].z + rows[r0+1].z) * 0.5f;
                res.w = (rows[r0].w + rows[r0+1].w) * 0.5f;
                o4[i * 14] = res;
            }
        }
    }
}

__global__ __launch_bounds__(256)
void denorm_relu_pool_v6(const float* __restrict__ p24,
                         const float* __restrict__ p32,
                         const float* __restrict__ p48,
                         const float* __restrict__ smean,
                         const float* __restrict__ sstd,
                         float* __restrict__ out)
{
    __shared__ float hp[48 * 56];   // 10752 B

    const int gnc = blockIdx.x;                 // n*256 + c, global
    const int grp = gnc >> 13;
    const int local = gnc & (NC_PER_GROUP - 1);
    const int tid = threadIdx.x;

    const float mean = __ldg(smean + gnc);
    const float sd   = __ldg(sstd + gnc);
    float* outp = out + (size_t)gnc * N_OUT;

    if (grp == 0) {
        run_group<24>(p24 + (size_t)local * (24 * 24), mean, sd, hp, outp, tid);
    } else if (grp == 1) {
        run_group<32>(p32 + (size_t)local * (32 * 32), mean, sd, hp, outp, tid);
    } else {
        run_group<48>(p48 + (size_t)local * (48 * 48), mean, sd, hp, outp, tid);
    }
}

extern "C" void kernel_launch(void* const* d_in, const int* in_sizes, int n_in,
                              void* d_out, int out_size)
{
    const float* p24   = (const float*)d_in[0];
    const float* p32   = (const float*)d_in[1];
    const float* p48   = (const float*)d_in[2];
    const float* smean = (const float*)d_in[3];
    const float* sstd  = (const float*)d_in[4];
    float* out = (float*)d_out;

    denorm_relu_pool_v6<<<3 * NC_PER_GROUP, 256>>>(p24, p32, p48,
                                                   smean, sstd, out);
}

// round 7
// speedup vs baseline: 1.3260x; 1.3260x over previous
#include <cuda_runtime.h>

#define OUT_S 56
#define N_OUT 3136
#define NC_PER_GROUP 8192

// Separable AdaptiveAvgPool2d(56) from S in {24,32,48}: S/56 = NUM/7, NUM=S/8.
// Phase A: thread=(row,quarter), global->regs->h-pool->smem.
// Phase B: 8 strips x 2 parts x 14 cols; each 7-output strip consumes exactly
// NUM rows, split at output 3|4 so each thread register-caches its rows.
// Blocks are group-interleaved so every scheduling wave carries a 1/3 mix of
// all three sides, keeping the HBM read:write ratio constant at ~0.42.

template<int S>
__device__ __forceinline__ void run_group(const float* __restrict__ src,
                                          float mean, float sd,
                                          float* __restrict__ hp,    // [S][56]
                                          float* __restrict__ outp,
                                          int tid)                   // 0..255
{
    constexpr int NUM = S / 8;              // 3, 4, 6
    constexpr int CPT = S / 4;              // 6, 8, 12
    constexpr int RE_P0 = (4 * NUM + 6) / 7; // rows needed by outputs 0..3
    constexpr int R0_P1 = (4 * NUM) / 7;     // first row needed by outputs 4..6
    constexpr int NR0 = RE_P0;
    constexpr int NR1 = NUM - R0_P1;

    // ---------------- Phase A ----------------
    if (tid < S * 4) {
        const int r = tid >> 2;
        const int q = tid & 3;
        const float* __restrict__ row = src + r * S + q * CPT;

        float v[CPT];
        if constexpr ((CPT & 3) == 0) {
            #pragma unroll
            for (int k = 0; k < CPT / 4; k++) {
                float4 t = ((const float4*)row)[k];
                v[4*k+0] = t.x; v[4*k+1] = t.y; v[4*k+2] = t.z; v[4*k+3] = t.w;
            }
        } else {
            #pragma unroll
            for (int k = 0; k < CPT / 2; k++) {
                float2 t = ((const float2*)row)[k];
                v[2*k+0] = t.x; v[2*k+1] = t.y;
            }
        }
        #pragma unroll
        for (int k = 0; k < CPT; k++)
            v[k] = fmaxf(fmaf(v[k], sd, mean), 0.0f);

        float o[14];
        #pragma unroll
        for (int jr = 0; jr < 14; jr++) {
            const int c0 = (jr * NUM) / 7;
            const int w  = ((jr + 1) * NUM + 6) / 7 - c0;
            o[jr] = (w == 2) ? (v[c0] + v[c0 + 1]) * 0.5f : v[c0];
        }

        float* dst = hp + r * 56 + q * 14;
        if ((q & 1) == 0) {
            *(float4*)(dst + 0)  = make_float4(o[0],  o[1],  o[2],  o[3]);
            *(float4*)(dst + 4)  = make_float4(o[4],  o[5],  o[6],  o[7]);
            *(float4*)(dst + 8)  = make_float4(o[8],  o[9],  o[10], o[11]);
            *(float2*)(dst + 12) = make_float2(o[12], o[13]);
        } else {
            *(float2*)(dst + 0)  = make_float2(o[0],  o[1]);
            *(float4*)(dst + 2)  = make_float4(o[2],  o[3],  o[4],  o[5]);
            *(float4*)(dst + 6)  = make_float4(o[6],  o[7],  o[8],  o[9]);
            *(float4*)(dst + 10) = make_float4(o[10], o[11], o[12], o[13]);
        }
    }
    __syncthreads();

    // ---------------- Phase B: split-strip, register-cached rows ----------------
    if (tid < 224) {
        const int strip = tid / 28;           // 0..7
        const int rem   = tid - strip * 28;
        const int part  = rem / 14;           // 0: outputs 0..3, 1: outputs 4..6
        const int col   = rem - part * 14;    // float4 column, fastest-varying

        float4* __restrict__ o4 = (float4*)outp + (strip * 7) * 14 + col;

        if (part == 0) {
            const float* base = hp + (strip * NUM) * 56 + col * 4;
            float4 rows[NR0];
            #pragma unroll
            for (int k = 0; k < NR0; k++)
                rows[k] = *(const float4*)(base + k * 56);

            #pragma unroll
            for (int i = 0; i < 4; i++) {
                const int r0 = (i * NUM) / 7;
                const int w  = ((i + 1) * NUM + 6) / 7 - r0;
                float4 res;
                if (w == 2) {
                    res.x = (rows[r0].x + rows[r0+1].x) * 0.5f;
                    res.y = (rows[r0].y + rows[r0+1].y) * 0.5f;
                    res.z = (rows[r0].z + rows[r0+1].z) * 0.5f;
                    res.w = (rows[r0].w + rows[r0+1].w) * 0.5f;
                } else {
                    res = rows[r0];
                }
                o4[i * 14] = res;
            }
        } else {
            const float* base = hp + (strip * NUM + R0_P1) * 56 + col * 4;
            float4 rows[NR1];
            #pragma unroll
            for (int k = 0; k < NR1; k++)
                rows[k] = *(const float4*)(base + k * 56);

            #pragma unroll
            for (int i = 4; i < 7; i++) {
                const int r0 = (i * NUM) / 7 - R0_P1;
                const int w  = ((i + 1) * NUM + 6) / 7 - (i * NUM) / 7;
                float4 res;
                if (w == 2) {
                    res.x = (rows[r0].x + rows[r0+1].x) * 0.5f;
                    res.y = (rows[r0].y + rows[r0+1].y) * 0.5f;
                    res.z = (rows[r0].z + rows[r0+1].z) * 0.5f;
                    res.w = (rows[r0].w + rows[r0+1].w) * 0.5f;
                } else {
                    res = rows[r0];
                }
                o4[i * 14] = res;
            }
        }
    }
}

__global__ __launch_bounds__(256)
void denorm_relu_pool_v7(const float* __restrict__ p24,
                         const float* __restrict__ p32,
                         const float* __restrict__ p48,
                         const float* __restrict__ smean,
                         const float* __restrict__ sstd,
                         float* __restrict__ out)
{
    __shared__ float hp[48 * 56];   // 10752 B

    // Group-interleaved mapping: adjacent blocks hit different groups, so each
    // scheduling wave carries a balanced read:write mix. Same-group blocks
    // remain address-sequential (local increments by 1 every 3 blocks).
    const int bid   = blockIdx.x;
    const int grp   = bid % 3;
    const int local = bid / 3;                  // 0..8191
    const int gnc   = grp * NC_PER_GROUP + local;
    const int tid   = threadIdx.x;

    const float mean = __ldg(smean + gnc);
    const float sd   = __ldg(sstd + gnc);
    float* outp = out + (size_t)gnc * N_OUT;

    if (grp == 0) {
        run_group<24>(p24 + (size_t)local * (24 * 24), mean, sd, hp, outp, tid);
    } else if (grp == 1) {
        run_group<32>(p32 + (size_t)local * (32 * 32), mean, sd, hp, outp, tid);
    } else {
        run_group<48>(p48 + (size_t)local * (48 * 48), mean, sd, hp, outp, tid);
    }
}

extern "C" void kernel_launch(void* const* d_in, const int* in_sizes, int n_in,
                              void* d_out, int out_size)
{
    const float* p24   = (const float*)d_in[0];
    const float* p32   = (const float*)d_in[1];
    const float* p48   = (const float*)d_in[2];
    const float* smean = (const float*)d_in[3];
    const float* sstd  = (const float*)d_in[4];
    float* out = (float*)d_out;

    denorm_relu_pool_v7<<<3 * NC_PER_GROUP, 256>>>(p24, p32, p48,
                                                   smean, sstd, out);
}